// round 2
// baseline (speedup 1.0000x reference)
#include <cuda_runtime.h>

// Hand_Input_Sorter: per-frame conditional half-swap (65 <-> 65 floats).
// Strategy: stage 16 frames (2080 floats, 8320B -> 16B aligned) per block through
// padded shared memory so that BOTH global loads and stores are aligned,
// coalesced float4 with streaming hints. The odd-offset permutation is done in
// smem; +1-per-32 padding keeps both scatter-STS and gather-LDS conflict-free.

static constexpr int FRAME_LEN = 130;
static constexpr int HALF      = 65;
static constexpr int FPB       = 16;                 // frames per block
static constexpr int FLOATS    = FPB * FRAME_LEN;    // 2080
static constexpr int VEC4      = FLOATS / 4;         // 520
static constexpr int THREADS   = 256;

__device__ __forceinline__ int spad(int w) { return w + (w >> 5); }

__device__ __forceinline__ bool compute_skip(float h0, float p0, float h1, float p1)
{
    bool nan0 = isnan(h0);
    bool nan1 = isnan(h1);
    // skip1: h1 > h0 (IEEE: false if either NaN, matches jnp)
    bool skip = (h1 > h0);
    // skip2: both NaN
    skip |= (nan0 && nan1);
    // skip3: only hand1 present, labeled right
    skip |= (nan0 && (h1 == 1.0f));
    // skip4: only hand0 present, labeled left
    skip |= (nan1 && (h0 == 0.0f));
    // skip5/6: both present, equal labels, prob ordering
    if (!nan0 && !nan1 && (h0 == h1)) {
        skip |= ((h0 == 0.0f) && (p0 > p1));
        skip |= ((h0 == 1.0f) && (p0 < p1));
    }
    return skip;
}

__global__ __launch_bounds__(THREADS) void hand_sorter_smem(
    const float* __restrict__ X,
    float* __restrict__ out,
    int n_frames)
{
    __shared__ float s[FLOATS + (FLOATS >> 5)];   // +1 word per 32 padding
    __shared__ int   sskip[FPB];

    const int tid   = threadIdx.x;
    const long long fbase = (long long)blockIdx.x * FPB;
    const int  nfb  = min(FPB, n_frames - (int)fbase);
    const float* __restrict__ src = X   + fbase * FRAME_LEN;
    float*       __restrict__ dst = out + fbase * FRAME_LEN;

    if (nfb == FPB) {
        // ---- fast path: full block, 16B-aligned float4 both directions ----
        const float4* __restrict__ in4 = (const float4*)src;

        #pragma unroll 2
        for (int i = tid; i < VEC4; i += THREADS) {
            float4 v = __ldcs(&in4[i]);
            int w = i * 4;
            s[spad(w + 0)] = v.x;
            s[spad(w + 1)] = v.y;
            s[spad(w + 2)] = v.z;
            s[spad(w + 3)] = v.w;
        }
        __syncthreads();

        if (tid < FPB) {
            int b = tid * FRAME_LEN;
            sskip[tid] = compute_skip(s[spad(b)], s[spad(b + 1)],
                                      s[spad(b + HALF)], s[spad(b + HALF + 1)]);
        }
        __syncthreads();

        float4* __restrict__ o4 = (float4*)dst;
        #pragma unroll 2
        for (int i = tid; i < VEC4; i += THREADS) {
            float r[4];
            #pragma unroll
            for (int c = 0; c < 4; c++) {
                unsigned k   = (unsigned)(i * 4 + c);
                unsigned f   = k / (unsigned)FRAME_LEN;   // magic-mul division
                int      off = (int)(k - f * FRAME_LEN);
                int so = sskip[f] ? off : (off < HALF ? off + HALF : off - HALF);
                r[c] = s[spad((int)f * FRAME_LEN + so)];
            }
            float4 v;
            v.x = r[0]; v.y = r[1]; v.z = r[2]; v.w = r[3];
            __stcs(&o4[i], v);
        }
    } else if (nfb > 0) {
        // ---- tail path: partial block, scalar (correct for any n_frames) ----
        const int nflt = nfb * FRAME_LEN;
        for (int j = tid; j < nflt; j += THREADS)
            s[spad(j)] = src[j];
        __syncthreads();
        if (tid < nfb) {
            int b = tid * FRAME_LEN;
            sskip[tid] = compute_skip(s[spad(b)], s[spad(b + 1)],
                                      s[spad(b + HALF)], s[spad(b + HALF + 1)]);
        }
        __syncthreads();
        for (int j = tid; j < nflt; j += THREADS) {
            unsigned f   = (unsigned)j / (unsigned)FRAME_LEN;
            int      off = j - (int)f * FRAME_LEN;
            int so = sskip[f] ? off : (off < HALF ? off + HALF : off - HALF);
            dst[j] = s[spad((int)f * FRAME_LEN + so)];
        }
    }
}

extern "C" void kernel_launch(void* const* d_in, const int* in_sizes, int n_in,
                              void* d_out, int out_size)
{
    const float* X = (const float*)d_in[0];
    // d_in[1] (swap_pattern int32[130]) is the fixed 65<->65 half swap; computed
    // analytically, so it isn't gathered.
    float* out = (float*)d_out;

    int n_frames = in_sizes[0] / FRAME_LEN;
    int blocks   = (n_frames + FPB - 1) / FPB;

    hand_sorter_smem<<<blocks, THREADS>>>(X, out, n_frames);
}

// round 3
// speedup vs baseline: 1.1943x; 1.1943x over previous
#include <cuda_runtime.h>

// Hand_Input_Sorter: per-frame conditional 65<->65 half-swap of [*,130] fp32.
// Warp-per-frame (2 frames/warp), float2 global accesses (frame base f*130 is
// always even -> 8B aligned), predicate scalars extracted via shuffle from the
// already-loaded registers, streaming cache hints. Pure HBM-bound stream.

static constexpr int FRAME_LEN = 130;

__device__ __forceinline__ bool compute_skip(float h0, float p0, float h1, float p1)
{
    bool nan0 = isnan(h0);
    bool nan1 = isnan(h1);
    bool skip = (h1 > h0);                 // false if either NaN (IEEE, matches jnp)
    skip |= (nan0 && nan1);                // both missing
    skip |= (nan0 && (h1 == 1.0f));        // only hand1, labeled right
    skip |= (nan1 && (h0 == 0.0f));        // only hand0, labeled left
    if (!nan0 && !nan1 && (h0 == h1)) {
        skip |= ((h0 == 0.0f) && (p0 > p1));
        skip |= ((h0 == 1.0f) && (p0 < p1));
    }
    return skip;
}

// Store one frame. Pairs: a = pair[lane] (elems 2l,2l+1), b = pair[lane+32]
// (elems 2l+64, 2l+65), c = pair[64] (elems 128,129; lane 0 only).
__device__ __forceinline__ void store_frame(float* __restrict__ o, int lane,
                                            float2 a, float2 b, float2 c, bool skip)
{
    if (skip) {
        float2* o2 = (float2*)o;
        __stcs(&o2[lane], a);
        __stcs(&o2[lane + 32], b);
        if (lane == 0) __stcs(&o2[64], c);
    } else {
        // a: elems (2l, 2l+1), both < 65 -> dst +65: (2l+65, 2l+66)
        __stcs(&o[2 * lane + 65], a.x);
        __stcs(&o[2 * lane + 66], a.y);
        if (lane == 0) {
            // b lane0 = pair32: elems (64, 65) -> dst (129, 0)
            __stcs(&o[129], b.x);
            __stcs(&o[0],   b.y);
            // c = pair64: elems (128, 129) -> dst (63, 64)
            __stcs(&o[63], c.x);
            __stcs(&o[64], c.y);
        } else {
            // b lanes>=1 = pair p=l+32: elems (2p, 2p+1) >= 66 -> dst -65: (2l-1, 2l)
            __stcs(&o[2 * lane - 1], b.x);
            __stcs(&o[2 * lane],     b.y);
        }
    }
}

__global__ __launch_bounds__(256) void hand_sorter_v3(
    const float* __restrict__ X,
    float* __restrict__ out,
    int n_frames)
{
    const int gw   = blockIdx.x * (blockDim.x >> 5) + (threadIdx.x >> 5);
    const int lane = threadIdx.x & 31;
    const int f0   = gw * 2;
    if (f0 >= n_frames) return;
    const bool has2 = (f0 + 1) < n_frames;

    const float2* __restrict__ i0 = (const float2*)(X + (size_t)f0 * FRAME_LEN);
    const float2* __restrict__ i1 = (const float2*)(X + (size_t)(f0 + 1) * FRAME_LEN);

    // Front-batch all loads (MLP ~6 per lane).
    float2 a0 = __ldcs(&i0[lane]);
    float2 b0 = __ldcs(&i0[lane + 32]);
    float2 a1 = make_float2(0.f, 0.f), b1 = make_float2(0.f, 0.f);
    if (has2) {
        a1 = __ldcs(&i1[lane]);
        b1 = __ldcs(&i1[lane + 32]);
    }
    float2 c0 = make_float2(0.f, 0.f), c1 = make_float2(0.f, 0.f);
    if (lane == 0) {
        c0 = __ldcs(&i0[64]);
        if (has2) c1 = __ldcs(&i1[64]);
    }

    const unsigned FULL = 0xFFFFFFFFu;
    // h0=elem0=a.x@l0, p0=elem1=a.y@l0, h1=elem65=pair32.y=b.y@l0, p1=elem66=pair33.x=b.x@l1
    bool skip0 = compute_skip(__shfl_sync(FULL, a0.x, 0), __shfl_sync(FULL, a0.y, 0),
                              __shfl_sync(FULL, b0.y, 0), __shfl_sync(FULL, b0.x, 1));
    bool skip1 = false;
    if (has2)
        skip1 = compute_skip(__shfl_sync(FULL, a1.x, 0), __shfl_sync(FULL, a1.y, 0),
                             __shfl_sync(FULL, b1.y, 0), __shfl_sync(FULL, b1.x, 1));

    store_frame(out + (size_t)f0 * FRAME_LEN, lane, a0, b0, c0, skip0);
    if (has2)
        store_frame(out + (size_t)(f0 + 1) * FRAME_LEN, lane, a1, b1, c1, skip1);
}

extern "C" void kernel_launch(void* const* d_in, const int* in_sizes, int n_in,
                              void* d_out, int out_size)
{
    const float* X = (const float*)d_in[0];
    // d_in[1] (swap_pattern int32[130]) is the fixed 65<->65 half swap; computed
    // analytically, so it isn't gathered.
    float* out = (float*)d_out;

    int n_frames = in_sizes[0] / FRAME_LEN;
    int n_warps  = (n_frames + 1) / 2;
    int warps_per_block = 256 / 32;
    int blocks = (n_warps + warps_per_block - 1) / warps_per_block;

    hand_sorter_v3<<<blocks, 256>>>(X, out, n_frames);
}

// round 4
// speedup vs baseline: 1.2177x; 1.0196x over previous
#include <cuda_runtime.h>

// Hand_Input_Sorter: per-frame conditional 65<->65 half-swap of [*,130] fp32.
// Warp-per-frame (2 frames/warp). ALL stores are the same aligned float2
// pattern (o2[lane], o2[lane+32], o2[64]); the swap permutation is realized by
// recombining register halves via warp shuffles instead of scattered STG.32.

static constexpr int FRAME_LEN = 130;
static constexpr unsigned FULL = 0xFFFFFFFFu;

__device__ __forceinline__ bool compute_skip(float h0, float p0, float h1, float p1)
{
    bool nan0 = isnan(h0);
    bool nan1 = isnan(h1);
    bool skip = (h1 > h0);                 // false if either NaN (IEEE, matches jnp)
    skip |= (nan0 && nan1);                // both missing
    skip |= (nan0 && (h1 == 1.0f));        // only hand1, labeled right
    skip |= (nan1 && (h0 == 0.0f));        // only hand0, labeled left
    if (!nan0 && !nan1 && (h0 == h1)) {
        skip |= ((h0 == 0.0f) && (p0 > p1));
        skip |= ((h0 == 1.0f) && (p0 < p1));
    }
    return skip;
}

// Pairs: a = pair[lane] (elems 2l, 2l+1), b = pair[lane+32] (elems 64+2l, 65+2l),
// c = pair[64] (elems 128,129), loaded uniformly on all lanes.
__device__ __forceinline__ void store_frame(float* __restrict__ o, int lane,
                                            float2 a, float2 b, float2 c, bool skip)
{
    float2* __restrict__ o2 = (float2*)o;
    if (skip) {
        __stcs(&o2[lane], a);
        __stcs(&o2[lane + 32], b);
        if (lane == 0) __stcs(&o2[64], c);
    } else {
        // out[j] = X[j+65] (j<65) / X[j-65] (j>=65), expressed as float2 slots:
        // slot p=lane (0..31):      {b[lane].y, b[lane+1].x}, b[32] := c
        float bx_next = __shfl_down_sync(FULL, b.x, 1);
        float2 v0 = make_float2(b.y, (lane == 31) ? c.x : bx_next);
        // slot p=lane+32 (32..63):  lane0 -> {c.y, a[0].x}; else {a[lane-1].y, a[lane].x}
        float ay_prev = __shfl_up_sync(FULL, a.y, 1);
        float a0x     = __shfl_sync(FULL, a.x, 0);
        float2 v1 = (lane == 0) ? make_float2(c.y, a0x)
                                : make_float2(ay_prev, a.x);
        // slot p=64: {a[31].y, b[0].x}
        float ay31 = __shfl_sync(FULL, a.y, 31);
        float b0x  = __shfl_sync(FULL, b.x, 0);
        __stcs(&o2[lane], v0);
        __stcs(&o2[lane + 32], v1);
        if (lane == 0) __stcs(&o2[64], make_float2(ay31, b0x));
    }
}

__global__ __launch_bounds__(256) void hand_sorter_v4(
    const float* __restrict__ X,
    float* __restrict__ out,
    int n_frames)
{
    const int gw   = blockIdx.x * (blockDim.x >> 5) + (threadIdx.x >> 5);
    const int lane = threadIdx.x & 31;
    const int f0   = gw * 2;
    if (f0 >= n_frames) return;
    const bool has2 = (f0 + 1) < n_frames;

    const float2* __restrict__ i0 = (const float2*)(X + (size_t)f0 * FRAME_LEN);
    const float2* __restrict__ i1 = (const float2*)(X + (size_t)(f0 + 1) * FRAME_LEN);

    // Front-batch all loads (MLP ~6 LDG.64 per lane; c loads are uniform-address).
    float2 a0 = __ldcs(&i0[lane]);
    float2 b0 = __ldcs(&i0[lane + 32]);
    float2 c0 = __ldcs(&i0[64]);
    float2 a1 = make_float2(0.f, 0.f), b1 = a1, c1 = a1;
    if (has2) {
        a1 = __ldcs(&i1[lane]);
        b1 = __ldcs(&i1[lane + 32]);
        c1 = __ldcs(&i1[64]);
    }

    // h0=a.x@0, p0=a.y@0, h1=elem65=b.y@0, p1=elem66=b.x@1
    bool skip0 = compute_skip(__shfl_sync(FULL, a0.x, 0), __shfl_sync(FULL, a0.y, 0),
                              __shfl_sync(FULL, b0.y, 0), __shfl_sync(FULL, b0.x, 1));
    bool skip1 = false;
    if (has2)
        skip1 = compute_skip(__shfl_sync(FULL, a1.x, 0), __shfl_sync(FULL, a1.y, 0),
                             __shfl_sync(FULL, b1.y, 0), __shfl_sync(FULL, b1.x, 1));

    store_frame(out + (size_t)f0 * FRAME_LEN, lane, a0, b0, c0, skip0);
    if (has2)
        store_frame(out + (size_t)(f0 + 1) * FRAME_LEN, lane, a1, b1, c1, skip1);
}

extern "C" void kernel_launch(void* const* d_in, const int* in_sizes, int n_in,
                              void* d_out, int out_size)
{
    const float* X = (const float*)d_in[0];
    // d_in[1] (swap_pattern int32[130]) is the fixed 65<->65 half swap; computed
    // analytically, so it isn't gathered.
    float* out = (float*)d_out;

    int n_frames = in_sizes[0] / FRAME_LEN;
    int n_warps  = (n_frames + 1) / 2;
    int warps_per_block = 256 / 32;
    int blocks = (n_warps + warps_per_block - 1) / warps_per_block;

    hand_sorter_v4<<<blocks, 256>>>(X, out, n_frames);
}